// round 3
// baseline (speedup 1.0000x reference)
#include <cuda_runtime.h>
#include <cstdint>

#define NB 8
#define CB 16
#define HB 256
#define WB 256
#define TOT (NB*CB*HB*WB)   // 8388608
#define IDX_OFF (TOT + 91)

#define TJ 64               // output tile width  (j)
#define TI 16               // output tile height (i)
#define TX 16               // threads in x, each computes 4 j-outputs
#define NTHR 256
#define PCOLS 68            // 66 used (TJ+2 halo), padded
#define PROWS (TI+2)        // 18
#define PSZ (PROWS*PCOLS)
#define SLOTS 512

__constant__ float c_filt[27];
__device__ float2 g_mm[SLOTS];   // per-block (min,max) partials

// ---------------------------------------------------------------------------
// Per-block min/max partials. Block 0 also passes through co_matrix and
// spatial_filter into the output tuple. x uniform [0,1): nonneg floats are
// order-isomorphic to their uint bits, but we reduce in float directly.
// ---------------------------------------------------------------------------
__global__ void __launch_bounds__(NTHR)
minmax_kernel(const float4* __restrict__ x, int n4,
              const float* __restrict__ co,
              const float* __restrict__ filt,
              float* __restrict__ out) {
    if (blockIdx.x == 0) {
        int t = threadIdx.x;
        if (t < 64) out[TOT + t] = co[t];
        if (t < 27) out[TOT + 64 + t] = filt[t];
    }
    float lmin = __int_as_float(0x7f800000);
    float lmax = 0.0f;
    int stride = gridDim.x * blockDim.x;
    for (int i = blockIdx.x * blockDim.x + threadIdx.x; i < n4; i += stride) {
        float4 v = x[i];
        lmin = fminf(lmin, fminf(fminf(v.x, v.y), fminf(v.z, v.w)));
        lmax = fmaxf(lmax, fmaxf(fmaxf(v.x, v.y), fmaxf(v.z, v.w)));
    }
#pragma unroll
    for (int o = 16; o; o >>= 1) {
        lmin = fminf(lmin, __shfl_xor_sync(0xffffffffu, lmin, o));
        lmax = fmaxf(lmax, __shfl_xor_sync(0xffffffffu, lmax, o));
    }
    __shared__ float smin[8], smax[8];
    int w = threadIdx.x >> 5;
    if ((threadIdx.x & 31) == 0) { smin[w] = lmin; smax[w] = lmax; }
    __syncthreads();
    if (threadIdx.x < 8) {
        lmin = smin[threadIdx.x];
        lmax = smax[threadIdx.x];
#pragma unroll
        for (int o = 4; o; o >>= 1) {
            lmin = fminf(lmin, __shfl_xor_sync(0xffu, lmin, o));
            lmax = fmaxf(lmax, __shfl_xor_sync(0xffu, lmax, o));
        }
        if (threadIdx.x == 0) g_mm[blockIdx.x] = make_float2(lmin, lmax);
    }
}

// ---------------------------------------------------------------------------
__device__ __forceinline__ uint32_t smem_u32(const void* p) {
    uint32_t a;
    asm("{ .reg .u64 t; cvta.to.shared.u64 t, %1; cvt.u32.u64 %0, t; }"
        : "=r"(a) : "l"(p));
    return a;
}

// co gather: addr = (p & 0x780) | rbase  -> single LOP3, then LDS.
// Requires co table 2048-byte aligned and rbase bits [10:7] == 0.
__device__ __forceinline__ float co_gather(uint32_t p, uint32_t rbase) {
    uint32_t a; float v;
    asm("lop3.b32 %0, %1, 0x780, %2, 0xEA;" : "=r"(a) : "r"(p), "r"(rbase));
    asm("ld.shared.f32 %0, [%1];" : "=f"(v) : "r"(a));
    return v;
}

// ---------------------------------------------------------------------------
// out[n,c,i,j] = [idx_p<8] * sum_{27 nbr} filt * co[idx_p, clamp(idx_nbr,7)] * x_nbr
// idx packed into mantissa bits [10:7] of x in the shared plane: one LDS per
// neighbor yields x (rel. perturbation <= 2.3e-4) AND the ready-shifted co
// column byte-offset via (p & 0x780).
// co table: 8 rows x 16 cols (cols 8..15 clamp to 7), 32x lane replication,
// 2048-aligned -> conflict-free; filter coefficients come from __constant__.
// ---------------------------------------------------------------------------
__global__ void __launch_bounds__(NTHR)
cooc_kernel(const float* __restrict__ x,
            const float* __restrict__ co,
            float* __restrict__ out) {
    __shared__ __align__(16) unsigned planes[4][PSZ];   // ~19.1 KB
    __shared__ float co_pad[8 * 16 * 32 + 512];         // 16 KB + align pad
    __shared__ float s_red[16];
    __shared__ float s_mm[2];

    const int tid  = threadIdx.x;
    const int lane = tid & 31;
    const int tx   = tid & (TX - 1);
    const int ty   = tid >> 4;

    const int j0 = blockIdx.x * TJ;
    const int i0 = blockIdx.y * TI;
    const int n  = blockIdx.z;

    // ---- reduce min/max partials (512 slots, 2 per thread) ----
    {
        float2 a = g_mm[tid];
        float2 b = g_mm[tid + NTHR];
        float mn = fminf(a.x, b.x);
        float mx = fmaxf(a.y, b.y);
#pragma unroll
        for (int o = 16; o; o >>= 1) {
            mn = fminf(mn, __shfl_xor_sync(0xffffffffu, mn, o));
            mx = fmaxf(mx, __shfl_xor_sync(0xffffffffu, mx, o));
        }
        if (lane == 0) { s_red[tid >> 5] = mn; s_red[8 + (tid >> 5)] = mx; }
    }

    // ---- fill replicated co LUT (independent of reduction) ----
    uintptr_t gp = (uintptr_t)co_pad;
    float* co_rep = (float*)((gp + 2047) & ~(uintptr_t)2047);
    const uint32_t co_u32 = smem_u32(co_rep);
    for (int e = tid; e < 4096; e += NTHR) {
        int c = (e >> 5) & 15;
        int r = e >> 9;
        co_rep[e] = co[r * 8 + (c < 8 ? c : 7)];
    }
    __syncthreads();
    if (tid < 2) {
        float v = s_red[tid * 8];
        if (tid == 0) {
            v = fminf(fminf(fminf(v, s_red[1]), fminf(s_red[2], s_red[3])),
                      fminf(fminf(s_red[4], s_red[5]), fminf(s_red[6], s_red[7])));
        } else {
            v = fmaxf(fmaxf(fmaxf(v, s_red[9]), fmaxf(s_red[10], s_red[11])),
                      fmaxf(fmaxf(s_red[12], s_red[13]), fmaxf(s_red[14], s_red[15])));
        }
        s_mm[tid] = v;
    }
    __syncthreads();
    const float xmin = s_mm[0];
    const float xmax = s_mm[1];

    const float* xb = x + (size_t)n * (CB * HB * WB);

    auto load_plane = [&](int cc, int buf) {
        unsigned* B = planes[buf];
        if ((unsigned)cc < (unsigned)CB) {
            const float* src = xb + cc * (HB * WB);
            for (int e = tid; e < PROWS * 66; e += NTHR) {
                int r = e / 66;
                int c = e - r * 66;
                int gi = i0 - 1 + r;
                int gj = j0 - 1 + c;
                unsigned pv = 0u;
                if ((unsigned)gi < (unsigned)HB && (unsigned)gj < (unsigned)WB) {
                    float xv = src[gi * WB + gj];
                    // exact JAX rounding: ((x - min) / max) * 8, floor
                    float t = __fdiv_rn(xv - xmin, xmax) * 8.0f;
                    int q = (int)t;            // t >= 0 -> trunc == floor
                    q = q < 15 ? q : 15;       // safety
                    pv = (__float_as_uint(xv) & ~0x780u) | ((unsigned)q << 7);
                }
                B[r * PCOLS + c] = pv;
            }
        } else {
            for (int e = tid; e < PROWS * 66; e += NTHR) {
                int r = e / 66;
                int c = e - r * 66;
                B[r * PCOLS + c] = 0u;
            }
        }
    };

    // plane p (p in [-1,16]) lives in buf (p+1)&3
    load_plane(-1, 0);
    load_plane(0, 1);
    load_plane(1, 2);

    const int gi    = i0 + ty;
    const int jbase = j0 + 4 * tx;
    const uint32_t lanebase = co_u32 + (lane << 2);

    for (int ci = 0; ci < CB; ci++) {
        __syncthreads();
        // prefetch plane ci+2 into buf (ci+3)&3; its previous content (plane
        // ci-1) had its last reader in iteration ci-1, before the sync above.
        if (ci <= CB - 2) load_plane(ci + 2, (ci + 3) & 3);

        // center row -> per-output co row bases
        const unsigned* Pc = planes[(ci + 1) & 3] + (ty + 1) * PCOLS + 4 * tx;
        uint4 ca  = *(const uint4*)Pc;
        uint2 cb2 = *(const uint2*)(Pc + 4);
        int r0 = (int)((ca.y  >> 7) & 15u);
        int r1 = (int)((ca.z  >> 7) & 15u);
        int r2 = (int)((ca.w  >> 7) & 15u);
        int r3 = (int)((cb2.x >> 7) & 15u);
        uint32_t rb0 = lanebase + ((uint32_t)(r0 < 8 ? r0 : 7) << 11);
        uint32_t rb1 = lanebase + ((uint32_t)(r1 < 8 ? r1 : 7) << 11);
        uint32_t rb2 = lanebase + ((uint32_t)(r2 < 8 ? r2 : 7) << 11);
        uint32_t rb3 = lanebase + ((uint32_t)(r3 < 8 ? r3 : 7) << 11);

        float acc0 = 0.f, acc1 = 0.f, acc2 = 0.f, acc3 = 0.f;
#pragma unroll
        for (int dc = 0; dc < 3; dc++) {
            const unsigned* P = planes[(ci + dc) & 3] + ty * PCOLS + 4 * tx;
#pragma unroll
            for (int di = 0; di < 3; di++) {
                uint4 a  = *(const uint4*)(P + di * PCOLS);
                uint2 b  = *(const uint2*)(P + di * PCOLS + 4);
                unsigned w0 = a.x, w1 = a.y, w2 = a.z, w3 = a.w, w4 = b.x, w5 = b.y;
                float f0 = c_filt[dc * 9 + di * 3 + 0];
                float f1 = c_filt[dc * 9 + di * 3 + 1];
                float f2 = c_filt[dc * 9 + di * 3 + 2];

                acc0 = fmaf(f0, co_gather(w0, rb0) * __uint_as_float(w0), acc0);
                acc0 = fmaf(f1, co_gather(w1, rb0) * __uint_as_float(w1), acc0);
                acc0 = fmaf(f2, co_gather(w2, rb0) * __uint_as_float(w2), acc0);

                acc1 = fmaf(f0, co_gather(w1, rb1) * __uint_as_float(w1), acc1);
                acc1 = fmaf(f1, co_gather(w2, rb1) * __uint_as_float(w2), acc1);
                acc1 = fmaf(f2, co_gather(w3, rb1) * __uint_as_float(w3), acc1);

                acc2 = fmaf(f0, co_gather(w2, rb2) * __uint_as_float(w2), acc2);
                acc2 = fmaf(f1, co_gather(w3, rb2) * __uint_as_float(w3), acc2);
                acc2 = fmaf(f2, co_gather(w4, rb2) * __uint_as_float(w4), acc2);

                acc3 = fmaf(f0, co_gather(w3, rb3) * __uint_as_float(w3), acc3);
                acc3 = fmaf(f1, co_gather(w4, rb3) * __uint_as_float(w4), acc3);
                acc3 = fmaf(f2, co_gather(w5, rb3) * __uint_as_float(w5), acc3);
            }
        }

        int o = ((n * CB + ci) * HB + gi) * WB + jbase;
        float4 res;
        res.x = r0 < 8 ? acc0 : 0.0f;
        res.y = r1 < 8 ? acc1 : 0.0f;
        res.z = r2 < 8 ? acc2 : 0.0f;
        res.w = r3 < 8 ? acc3 : 0.0f;
        *(float4*)(out + o) = res;
        out[IDX_OFF + o + 0] = (float)r0;   // IDX_OFF+o is 4B-aligned only
        out[IDX_OFF + o + 1] = (float)r1;
        out[IDX_OFF + o + 2] = (float)r2;
        out[IDX_OFF + o + 3] = (float)r3;
    }
}

// ---------------------------------------------------------------------------
extern "C" void kernel_launch(void* const* d_in, const int* in_sizes, int n_in,
                              void* d_out, int out_size) {
    const float* x    = (const float*)d_in[0];
    const float* co   = (const float*)d_in[1];
    const float* filt = (const float*)d_in[2];
    float* out        = (float*)d_out;

    cudaMemcpyToSymbolAsync(c_filt, filt, 27 * sizeof(float), 0,
                            cudaMemcpyDeviceToDevice);

    minmax_kernel<<<SLOTS, NTHR>>>((const float4*)x, TOT / 4, co, filt, out);

    dim3 grid(WB / TJ, HB / TI, NB);   // 4 x 16 x 8 = 512 blocks
    cooc_kernel<<<grid, NTHR>>>(x, co, out);
}

// round 4
// speedup vs baseline: 1.0512x; 1.0512x over previous
#include <cuda_runtime.h>
#include <cstdint>

#define NB 8
#define CB 16
#define HB 256
#define WB 256
#define TOT (NB*CB*HB*WB)   // 8388608
#define IDX_OFF (TOT + 91)

#define TJ 64               // output tile width  (j)
#define TI 8                // output tile height (i)
#define TX 16               // threads in x, each computes 4 j-outputs
#define NTHR 128
#define PCOLS 68            // 66 used (TJ+2 halo), padded
#define PROWS (TI+2)        // 10
#define PSZ (PROWS*PCOLS)
#define SLOTS 512

__constant__ float c_filt[27];
__device__ float2 g_mm[SLOTS];   // per-block (min,max) partials

// ---------------------------------------------------------------------------
// Per-block min/max partials; block 0 passes through co_matrix & filter.
// ---------------------------------------------------------------------------
__global__ void __launch_bounds__(256)
minmax_kernel(const float4* __restrict__ x, int n4,
              const float* __restrict__ co,
              const float* __restrict__ filt,
              float* __restrict__ out) {
    if (blockIdx.x == 0) {
        int t = threadIdx.x;
        if (t < 64) out[TOT + t] = co[t];
        if (t < 27) out[TOT + 64 + t] = filt[t];
    }
    float lmin = __int_as_float(0x7f800000);
    float lmax = 0.0f;
    int stride = gridDim.x * blockDim.x;
    for (int i = blockIdx.x * blockDim.x + threadIdx.x; i < n4; i += stride) {
        float4 v = x[i];
        lmin = fminf(lmin, fminf(fminf(v.x, v.y), fminf(v.z, v.w)));
        lmax = fmaxf(lmax, fmaxf(fmaxf(v.x, v.y), fmaxf(v.z, v.w)));
    }
#pragma unroll
    for (int o = 16; o; o >>= 1) {
        lmin = fminf(lmin, __shfl_xor_sync(0xffffffffu, lmin, o));
        lmax = fmaxf(lmax, __shfl_xor_sync(0xffffffffu, lmax, o));
    }
    __shared__ float smin[8], smax[8];
    int w = threadIdx.x >> 5;
    if ((threadIdx.x & 31) == 0) { smin[w] = lmin; smax[w] = lmax; }
    __syncthreads();
    if (threadIdx.x < 8) {
        lmin = smin[threadIdx.x];
        lmax = smax[threadIdx.x];
#pragma unroll
        for (int o = 4; o; o >>= 1) {
            lmin = fminf(lmin, __shfl_xor_sync(0xffu, lmin, o));
            lmax = fmaxf(lmax, __shfl_xor_sync(0xffu, lmax, o));
        }
        if (threadIdx.x == 0) g_mm[blockIdx.x] = make_float2(lmin, lmax);
    }
}

// ---------------------------------------------------------------------------
__device__ __forceinline__ uint32_t smem_u32(const void* p) {
    uint32_t a;
    asm("{ .reg .u64 t; cvta.to.shared.u64 t, %1; cvt.u32.u64 %0, t; }"
        : "=r"(a) : "l"(p));
    return a;
}

// co gather: addr = (p & 0x780) | rbase  -> single LOP3, then LDS.
// Requires co table 2048-byte aligned and rbase bits [10:7] == 0.
__device__ __forceinline__ float co_gather(uint32_t p, uint32_t rbase) {
    uint32_t a; float v;
    asm("lop3.b32 %0, %1, 0x780, %2, 0xEA;" : "=r"(a) : "r"(p), "r"(rbase));
    asm("ld.shared.f32 %0, [%1];" : "=f"(v) : "r"(a));
    return v;
}

// ---------------------------------------------------------------------------
// out[n,c,i,j] = [idx_p<8] * sum_{27 nbr} filt * co[idx_p, clamp(idx_nbr,7)] * x_nbr
// idx packed in mantissa bits [10:7] of x in shared planes (one LDS per
// neighbor gives x, perturbation <= 2.3e-4, AND the shifted co column offset).
// co table: 8 rows x 16 cols (cols 8..15 = clamp of 7), 32x lane replication,
// 2048-aligned -> conflict-free. Filter held in REGISTERS (asm fence stops
// ptxas from rematerializing half-rate LDC in the loop).
// ---------------------------------------------------------------------------
__global__ void __launch_bounds__(NTHR)
cooc_kernel(const float* __restrict__ x,
            const float* __restrict__ co,
            float* __restrict__ out) {
    __shared__ __align__(16) unsigned planes[4][PSZ];   // ~10.9 KB
    __shared__ float co_pad[8 * 16 * 32 + 512];         // 16 KB + align pad
    __shared__ float s_red[16];
    __shared__ float s_mm[2];

    const int tid  = threadIdx.x;
    const int lane = tid & 31;
    const int tx   = tid & (TX - 1);
    const int ty   = tid >> 4;

    const int j0 = blockIdx.x * TJ;
    const int i0 = blockIdx.y * TI;
    const int n  = blockIdx.z;

    // ---- reduce min/max partials (512 slots, 4 per thread) ----
    {
        float2 a = g_mm[tid];
        float2 b = g_mm[tid + 128];
        float2 c = g_mm[tid + 256];
        float2 d = g_mm[tid + 384];
        float mn = fminf(fminf(a.x, b.x), fminf(c.x, d.x));
        float mx = fmaxf(fmaxf(a.y, b.y), fmaxf(c.y, d.y));
#pragma unroll
        for (int o = 16; o; o >>= 1) {
            mn = fminf(mn, __shfl_xor_sync(0xffffffffu, mn, o));
            mx = fmaxf(mx, __shfl_xor_sync(0xffffffffu, mx, o));
        }
        if (lane == 0) { s_red[tid >> 5] = mn; s_red[8 + (tid >> 5)] = mx; }
    }

    // ---- fill replicated co LUT ----
    uintptr_t gp = (uintptr_t)co_pad;
    float* co_rep = (float*)((gp + 2047) & ~(uintptr_t)2047);
    const uint32_t co_u32 = smem_u32(co_rep);
    for (int e = tid; e < 4096; e += NTHR) {
        int c = (e >> 5) & 15;
        int r = e >> 9;
        co_rep[e] = co[r * 8 + (c < 8 ? c : 7)];
    }

    // ---- filter -> registers, fenced so it stays there ----
    float fr[27];
#pragma unroll
    for (int k = 0; k < 27; k++) {
        float v = c_filt[k];
        asm("mov.f32 %0, %0;" : "+f"(v));   // break const-prop / remat chain
        fr[k] = v;
    }

    __syncthreads();
    if (tid < 2) {
        float v;
        if (tid == 0) {
            v = fminf(fminf(fminf(s_red[0], s_red[1]), fminf(s_red[2], s_red[3])),
                      fminf(fminf(s_red[4], s_red[5]), fminf(s_red[6], s_red[7])));
        } else {
            v = fmaxf(fmaxf(fmaxf(s_red[8], s_red[9]), fmaxf(s_red[10], s_red[11])),
                      fmaxf(fmaxf(s_red[12], s_red[13]), fmaxf(s_red[14], s_red[15])));
        }
        s_mm[tid] = v;
    }
    __syncthreads();
    const float xmin = s_mm[0];
    const float xmax = s_mm[1];

    const float* xb = x + (size_t)n * (CB * HB * WB);

    auto load_plane = [&](int cc, int buf) {
        unsigned* B = planes[buf];
        if ((unsigned)cc < (unsigned)CB) {
            const float* src = xb + cc * (HB * WB);
            for (int e = tid; e < PROWS * 66; e += NTHR) {
                int r = e / 66;
                int c = e - r * 66;
                int gi = i0 - 1 + r;
                int gj = j0 - 1 + c;
                unsigned pv = 0u;
                if ((unsigned)gi < (unsigned)HB && (unsigned)gj < (unsigned)WB) {
                    float xv = src[gi * WB + gj];
                    // exact JAX rounding: ((x - min) / max) * 8, floor
                    float t = __fdiv_rn(xv - xmin, xmax) * 8.0f;
                    int q = (int)t;            // t >= 0 -> trunc == floor
                    q = q < 15 ? q : 15;       // safety
                    pv = (__float_as_uint(xv) & ~0x780u) | ((unsigned)q << 7);
                }
                B[r * PCOLS + c] = pv;
            }
        } else {
            for (int e = tid; e < PROWS * 66; e += NTHR) {
                int r = e / 66;
                int c = e - r * 66;
                B[r * PCOLS + c] = 0u;
            }
        }
    };

    // plane p (p in [-1,16]) lives in buf (p+1)&3
    load_plane(-1, 0);
    load_plane(0, 1);
    load_plane(1, 2);

    const int gi    = i0 + ty;
    const int jbase = j0 + 4 * tx;
    const uint32_t lanebase = co_u32 + (lane << 2);

    for (int ci = 0; ci < CB; ci++) {
        __syncthreads();
        // prefetch plane ci+2 into buf (ci+3)&3; previous content (plane ci-1)
        // had its last reader in iteration ci-1, before the sync above.
        if (ci <= CB - 2) load_plane(ci + 2, (ci + 3) & 3);

        // center row -> per-output co row bases
        const unsigned* Pc = planes[(ci + 1) & 3] + (ty + 1) * PCOLS + 4 * tx;
        uint4 ca  = *(const uint4*)Pc;
        uint2 cb2 = *(const uint2*)(Pc + 4);
        int r0 = (int)((ca.y  >> 7) & 15u);
        int r1 = (int)((ca.z  >> 7) & 15u);
        int r2 = (int)((ca.w  >> 7) & 15u);
        int r3 = (int)((cb2.x >> 7) & 15u);
        uint32_t rb0 = lanebase + ((uint32_t)(r0 < 8 ? r0 : 7) << 11);
        uint32_t rb1 = lanebase + ((uint32_t)(r1 < 8 ? r1 : 7) << 11);
        uint32_t rb2 = lanebase + ((uint32_t)(r2 < 8 ? r2 : 7) << 11);
        uint32_t rb3 = lanebase + ((uint32_t)(r3 < 8 ? r3 : 7) << 11);

        float acc0 = 0.f, acc1 = 0.f, acc2 = 0.f, acc3 = 0.f;
#pragma unroll
        for (int dc = 0; dc < 3; dc++) {
            const unsigned* P = planes[(ci + dc) & 3] + ty * PCOLS + 4 * tx;
#pragma unroll
            for (int di = 0; di < 3; di++) {
                uint4 a  = *(const uint4*)(P + di * PCOLS);
                uint2 b  = *(const uint2*)(P + di * PCOLS + 4);
                unsigned w0 = a.x, w1 = a.y, w2 = a.z, w3 = a.w, w4 = b.x, w5 = b.y;
                float f0 = fr[dc * 9 + di * 3 + 0];
                float f1 = fr[dc * 9 + di * 3 + 1];
                float f2 = fr[dc * 9 + di * 3 + 2];

                acc0 = fmaf(f0, co_gather(w0, rb0) * __uint_as_float(w0), acc0);
                acc0 = fmaf(f1, co_gather(w1, rb0) * __uint_as_float(w1), acc0);
                acc0 = fmaf(f2, co_gather(w2, rb0) * __uint_as_float(w2), acc0);

                acc1 = fmaf(f0, co_gather(w1, rb1) * __uint_as_float(w1), acc1);
                acc1 = fmaf(f1, co_gather(w2, rb1) * __uint_as_float(w2), acc1);
                acc1 = fmaf(f2, co_gather(w3, rb1) * __uint_as_float(w3), acc1);

                acc2 = fmaf(f0, co_gather(w2, rb2) * __uint_as_float(w2), acc2);
                acc2 = fmaf(f1, co_gather(w3, rb2) * __uint_as_float(w3), acc2);
                acc2 = fmaf(f2, co_gather(w4, rb2) * __uint_as_float(w4), acc2);

                acc3 = fmaf(f0, co_gather(w3, rb3) * __uint_as_float(w3), acc3);
                acc3 = fmaf(f1, co_gather(w4, rb3) * __uint_as_float(w4), acc3);
                acc3 = fmaf(f2, co_gather(w5, rb3) * __uint_as_float(w5), acc3);
            }
        }

        int o = ((n * CB + ci) * HB + gi) * WB + jbase;
        float4 res;
        res.x = r0 < 8 ? acc0 : 0.0f;
        res.y = r1 < 8 ? acc1 : 0.0f;
        res.z = r2 < 8 ? acc2 : 0.0f;
        res.w = r3 < 8 ? acc3 : 0.0f;
        *(float4*)(out + o) = res;
        out[IDX_OFF + o + 0] = (float)r0;   // IDX_OFF+o only 4B-aligned
        out[IDX_OFF + o + 1] = (float)r1;
        out[IDX_OFF + o + 2] = (float)r2;
        out[IDX_OFF + o + 3] = (float)r3;
    }
}

// ---------------------------------------------------------------------------
extern "C" void kernel_launch(void* const* d_in, const int* in_sizes, int n_in,
                              void* d_out, int out_size) {
    const float* x    = (const float*)d_in[0];
    const float* co   = (const float*)d_in[1];
    const float* filt = (const float*)d_in[2];
    float* out        = (float*)d_out;

    cudaMemcpyToSymbolAsync(c_filt, filt, 27 * sizeof(float), 0,
                            cudaMemcpyDeviceToDevice);

    minmax_kernel<<<SLOTS, 256>>>((const float4*)x, TOT / 4, co, filt, out);

    dim3 grid(WB / TJ, HB / TI, NB);   // 4 x 32 x 8 = 1024 blocks
    cooc_kernel<<<grid, NTHR>>>(x, co, out);
}

// round 5
// speedup vs baseline: 1.0738x; 1.0215x over previous
#include <cuda_runtime.h>
#include <cstdint>

#define NB 8
#define CB 16
#define HB 256
#define WB 256
#define TOT (NB*CB*HB*WB)   // 8388608
#define IDX_OFF (TOT + 91)

#define TJ 64               // output tile width  (j)
#define TI 8                // output tile height (i)
#define TX 16               // threads in x, each computes 4 j-outputs
#define NTHR 128
#define PCOLS 68            // 66 used (TJ+2 halo), padded
#define PROWS (TI+2)        // 10
#define PSZ (PROWS*PCOLS)
#define SLOTS 512

__device__ float2 g_mm[SLOTS];   // per-block (min,max) partials

// ---------------------------------------------------------------------------
// Per-block min/max partials; block 0 passes through co_matrix & filter.
// ---------------------------------------------------------------------------
__global__ void __launch_bounds__(256)
minmax_kernel(const float4* __restrict__ x, int n4,
              const float* __restrict__ co,
              const float* __restrict__ filt,
              float* __restrict__ out) {
    if (blockIdx.x == 0) {
        int t = threadIdx.x;
        if (t < 64) out[TOT + t] = co[t];
        if (t < 27) out[TOT + 64 + t] = filt[t];
    }
    float lmin = __int_as_float(0x7f800000);
    float lmax = 0.0f;
    int stride = gridDim.x * blockDim.x;
    for (int i = blockIdx.x * blockDim.x + threadIdx.x; i < n4; i += stride) {
        float4 v = x[i];
        lmin = fminf(lmin, fminf(fminf(v.x, v.y), fminf(v.z, v.w)));
        lmax = fmaxf(lmax, fmaxf(fmaxf(v.x, v.y), fmaxf(v.z, v.w)));
    }
#pragma unroll
    for (int o = 16; o; o >>= 1) {
        lmin = fminf(lmin, __shfl_xor_sync(0xffffffffu, lmin, o));
        lmax = fmaxf(lmax, __shfl_xor_sync(0xffffffffu, lmax, o));
    }
    __shared__ float smin[8], smax[8];
    int w = threadIdx.x >> 5;
    if ((threadIdx.x & 31) == 0) { smin[w] = lmin; smax[w] = lmax; }
    __syncthreads();
    if (threadIdx.x < 8) {
        lmin = smin[threadIdx.x];
        lmax = smax[threadIdx.x];
#pragma unroll
        for (int o = 4; o; o >>= 1) {
            lmin = fminf(lmin, __shfl_xor_sync(0xffu, lmin, o));
            lmax = fmaxf(lmax, __shfl_xor_sync(0xffu, lmax, o));
        }
        if (threadIdx.x == 0) g_mm[blockIdx.x] = make_float2(lmin, lmax);
    }
}

// ---------------------------------------------------------------------------
__device__ __forceinline__ uint32_t smem_u32(const void* p) {
    uint32_t a;
    asm("{ .reg .u64 t; cvta.to.shared.u64 t, %1; cvt.u32.u64 %0, t; }"
        : "=r"(a) : "l"(p));
    return a;
}

// co gather: addr = (p & 0x380) | rbase  -> single LOP3, then LDS.
// Requires table base 1024-aligned and rbase bits [9:7] clear of col bits.
__device__ __forceinline__ float co_gather(uint32_t p, uint32_t rbase) {
    uint32_t a; float v;
    asm("lop3.b32 %0, %1, 0x380, %2, 0xEA;" : "=r"(a) : "r"(p), "r"(rbase));
    asm("ld.shared.f32 %0, [%1];" : "=f"(v) : "r"(a));
    return v;
}

// ---------------------------------------------------------------------------
// out[n,c,i,j] = [idx_p<8] * sum_{27 nbr} filt * co[idx_p, clamp(idx_nbr,7)] * x_nbr
//
// Packed plane word: x mantissa bits [10:7] replaced by
//   bits [9:7]  = clamped column  min(idx,7)   (JAX OOB clamp baked in)
//   bit  [10]   = (idx == 8) flag  (center mask + raw idx reconstruction)
// -> one LDS per neighbor yields x (pert. <= 2.4e-4) AND the table column
//    byte-offset (p & 0x380); raw idx = col + flag.
// co table: 8 rows x 8 cols x 32 lane replicas (8 KB), 1024-aligned,
//   conflict-free; addr = rbase | (p & 0x380), row stride 1024 = (p&0x380)<<3.
// Filter: smem broadcasts (frees ~20 regs -> occupancy).
// ---------------------------------------------------------------------------
__global__ void __launch_bounds__(NTHR, 10)
cooc_kernel(const float* __restrict__ x,
            const float* __restrict__ co,
            const float* __restrict__ filt,
            float* __restrict__ out) {
    __shared__ __align__(16) unsigned planes[4][PSZ];   // ~10.9 KB
    __shared__ float co_pad[2048 + 256];                // 8 KB + align pad
    __shared__ float sfilt[27];
    __shared__ float s_red[16];
    __shared__ float s_mm[2];

    const int tid  = threadIdx.x;
    const int lane = tid & 31;
    const int tx   = tid & (TX - 1);
    const int ty   = tid >> 4;

    const int j0 = blockIdx.x * TJ;
    const int i0 = blockIdx.y * TI;
    const int n  = blockIdx.z;

    // ---- reduce min/max partials (512 slots, 4 per thread) ----
    {
        float2 a = g_mm[tid];
        float2 b = g_mm[tid + 128];
        float2 c = g_mm[tid + 256];
        float2 d = g_mm[tid + 384];
        float mn = fminf(fminf(a.x, b.x), fminf(c.x, d.x));
        float mx = fmaxf(fmaxf(a.y, b.y), fmaxf(c.y, d.y));
#pragma unroll
        for (int o = 16; o; o >>= 1) {
            mn = fminf(mn, __shfl_xor_sync(0xffffffffu, mn, o));
            mx = fmaxf(mx, __shfl_xor_sync(0xffffffffu, mx, o));
        }
        if (lane == 0) { s_red[tid >> 5] = mn; s_red[8 + (tid >> 5)] = mx; }
    }

    // ---- fill replicated co LUT (8 rows x 8 cols x 32 lanes) ----
    uintptr_t gp = (uintptr_t)co_pad;
    float* co_rep = (float*)((gp + 1023) & ~(uintptr_t)1023);
    const uint32_t co_u32 = smem_u32(co_rep);
    for (int e = tid; e < 2048; e += NTHR) {
        int l = e & 31;
        int c = (e >> 5) & 7;
        int r = e >> 8;
        co_rep[r * 256 + c * 32 + l] = co[r * 8 + c];
    }
    if (tid < 27) sfilt[tid] = filt[tid];

    __syncthreads();
    if (tid < 2) {
        float v;
        if (tid == 0) {
            v = fminf(fminf(fminf(s_red[0], s_red[1]), fminf(s_red[2], s_red[3])),
                      fminf(fminf(s_red[4], s_red[5]), fminf(s_red[6], s_red[7])));
        } else {
            v = fmaxf(fmaxf(fmaxf(s_red[8], s_red[9]), fmaxf(s_red[10], s_red[11])),
                      fmaxf(fmaxf(s_red[12], s_red[13]), fmaxf(s_red[14], s_red[15])));
        }
        s_mm[tid] = v;
    }
    __syncthreads();
    const float xmin = s_mm[0];
    const float xmax = s_mm[1];

    const float* xb = x + (size_t)n * (CB * HB * WB);

    auto load_plane = [&](int cc, int buf) {
        unsigned* B = planes[buf];
        if ((unsigned)cc < (unsigned)CB) {
            const float* src = xb + cc * (HB * WB);
            for (int e = tid; e < PROWS * 66; e += NTHR) {
                int r = e / 66;
                int c = e - r * 66;
                int gi = i0 - 1 + r;
                int gj = j0 - 1 + c;
                unsigned pv = 0u;
                if ((unsigned)gi < (unsigned)HB && (unsigned)gj < (unsigned)WB) {
                    float xv = src[gi * WB + gj];
                    // exact JAX rounding: ((x - min) / max) * 8, floor
                    float t = __fdiv_rn(xv - xmin, xmax) * 8.0f;
                    int q = (int)t;                 // q in [0, 8]
                    unsigned qc = (q < 8) ? (unsigned)q : 7u;   // clamped col
                    unsigned fl = (q >= 8) ? 1u : 0u;           // idx==8 flag
                    pv = (__float_as_uint(xv) & ~0x780u) | (qc << 7) | (fl << 10);
                }
                B[r * PCOLS + c] = pv;
            }
        } else {
            for (int e = tid; e < PROWS * 66; e += NTHR) {
                int r = e / 66;
                int c = e - r * 66;
                B[r * PCOLS + c] = 0u;
            }
        }
    };

    // plane p (p in [-1,16]) lives in buf (p+1)&3
    load_plane(-1, 0);
    load_plane(0, 1);
    load_plane(1, 2);

    const int gi    = i0 + ty;
    const int jbase = j0 + 4 * tx;
    const uint32_t lanebase = co_u32 + (lane << 2);

    for (int ci = 0; ci < CB; ci++) {
        __syncthreads();
        // prefetch plane ci+2 into buf (ci+3)&3; previous content (plane ci-1)
        // had its last reader in iteration ci-1, before the sync above.
        if (ci <= CB - 2) load_plane(ci + 2, (ci + 3) & 3);

        // center row -> per-output co row bases (row stride 1024 = col<<3·128)
        const unsigned* Pc = planes[(ci + 1) & 3] + (ty + 1) * PCOLS + 4 * tx;
        uint4 ca  = *(const uint4*)Pc;
        uint2 cb2 = *(const uint2*)(Pc + 4);
        uint32_t rb0 = lanebase + ((ca.y  & 0x380u) << 3);
        uint32_t rb1 = lanebase + ((ca.z  & 0x380u) << 3);
        uint32_t rb2 = lanebase + ((ca.w  & 0x380u) << 3);
        uint32_t rb3 = lanebase + ((cb2.x & 0x380u) << 3);

        float acc0 = 0.f, acc1 = 0.f, acc2 = 0.f, acc3 = 0.f;
#pragma unroll
        for (int dc = 0; dc < 3; dc++) {
            const unsigned* P = planes[(ci + dc) & 3] + ty * PCOLS + 4 * tx;
#pragma unroll
            for (int di = 0; di < 3; di++) {
                uint4 a  = *(const uint4*)(P + di * PCOLS);
                uint2 b  = *(const uint2*)(P + di * PCOLS + 4);
                unsigned w0 = a.x, w1 = a.y, w2 = a.z, w3 = a.w, w4 = b.x, w5 = b.y;
                float f0 = sfilt[dc * 9 + di * 3 + 0];
                float f1 = sfilt[dc * 9 + di * 3 + 1];
                float f2 = sfilt[dc * 9 + di * 3 + 2];

                acc0 = fmaf(f0, co_gather(w0, rb0) * __uint_as_float(w0), acc0);
                acc0 = fmaf(f1, co_gather(w1, rb0) * __uint_as_float(w1), acc0);
                acc0 = fmaf(f2, co_gather(w2, rb0) * __uint_as_float(w2), acc0);

                acc1 = fmaf(f0, co_gather(w1, rb1) * __uint_as_float(w1), acc1);
                acc1 = fmaf(f1, co_gather(w2, rb1) * __uint_as_float(w2), acc1);
                acc1 = fmaf(f2, co_gather(w3, rb1) * __uint_as_float(w3), acc1);

                acc2 = fmaf(f0, co_gather(w2, rb2) * __uint_as_float(w2), acc2);
                acc2 = fmaf(f1, co_gather(w3, rb2) * __uint_as_float(w3), acc2);
                acc2 = fmaf(f2, co_gather(w4, rb2) * __uint_as_float(w4), acc2);

                acc3 = fmaf(f0, co_gather(w3, rb3) * __uint_as_float(w3), acc3);
                acc3 = fmaf(f1, co_gather(w4, rb3) * __uint_as_float(w4), acc3);
                acc3 = fmaf(f2, co_gather(w5, rb3) * __uint_as_float(w5), acc3);
            }
        }

        int o = ((n * CB + ci) * HB + gi) * WB + jbase;
        float4 res;
        res.x = (ca.y  & 0x400u) ? 0.0f : acc0;   // flag set -> idx==8 -> 0
        res.y = (ca.z  & 0x400u) ? 0.0f : acc1;
        res.z = (ca.w  & 0x400u) ? 0.0f : acc2;
        res.w = (cb2.x & 0x400u) ? 0.0f : acc3;
        *(float4*)(out + o) = res;
        // raw idx = clamped col + flag
        out[IDX_OFF + o + 0] = (float)(((ca.y  >> 7) & 7u) + ((ca.y  >> 10) & 1u));
        out[IDX_OFF + o + 1] = (float)(((ca.z  >> 7) & 7u) + ((ca.z  >> 10) & 1u));
        out[IDX_OFF + o + 2] = (float)(((ca.w  >> 7) & 7u) + ((ca.w  >> 10) & 1u));
        out[IDX_OFF + o + 3] = (float)(((cb2.x >> 7) & 7u) + ((cb2.x >> 10) & 1u));
    }
}

// ---------------------------------------------------------------------------
extern "C" void kernel_launch(void* const* d_in, const int* in_sizes, int n_in,
                              void* d_out, int out_size) {
    const float* x    = (const float*)d_in[0];
    const float* co   = (const float*)d_in[1];
    const float* filt = (const float*)d_in[2];
    float* out        = (float*)d_out;

    minmax_kernel<<<SLOTS, 256>>>((const float4*)x, TOT / 4, co, filt, out);

    dim3 grid(WB / TJ, HB / TI, NB);   // 4 x 32 x 8 = 1024 blocks
    cooc_kernel<<<grid, NTHR>>>(x, co, filt, out);
}